// round 3
// baseline (speedup 1.0000x reference)
#include <cuda_runtime.h>
#include <math.h>

#define NGRAPH 1024
#define DIM 64
#define INDIM 25
#define MAXN 100000
#define MAXE 1600000

// ---------------- scratch (device globals; no allocation allowed) ----------
__device__ __align__(16) float g_h0[MAXN * DIM];
__device__ __align__(16) float g_h1[MAXN * DIM];
__device__ int   g_counts[MAXN + 1];
__device__ int   g_rowptr[MAXN + 1];
__device__ int   g_cursor[MAXN + 1];
__device__ int   g_csr_src[MAXE];
__device__ int   g_start[NGRAPH + 1];
__device__ float g_hs[NGRAPH * DIM];
__device__ float g_cs[NGRAPH * DIM];
__device__ float g_qstar[NGRAPH * 2 * DIM];
__device__ int   g_is64;

// ---------------- helpers ---------------------------------------------------
__device__ __forceinline__ long long ld_idx(const void* p, long long i, int is64) {
    return is64 ? ((const long long*)p)[i] : (long long)((const int*)p)[i];
}
__device__ __forceinline__ float sigm(float x) { return 1.0f / (1.0f + __expf(-x)); }

// ---------------- dtype detection (int32 vs int64 indices) ------------------
__global__ void detect_kernel(const void* batch, int N) {
    __shared__ int nz;
    if (threadIdx.x == 0) nz = 0;
    __syncthreads();
    int limit = N < 20000 ? N : 20000;
    int cnt = 0;
    for (int i = 1 + 2 * (int)threadIdx.x; i < limit; i += 2 * blockDim.x)
        if (((const int*)batch)[i] != 0) cnt++;
    if (cnt) atomicAdd(&nz, cnt);
    __syncthreads();
    if (threadIdx.x == 0) g_is64 = (nz == 0) ? 1 : 0;
}

// ----- zero LSTM state, q_star, degree counts (MUST cover all replays) ------
__global__ void init_kernel(int N) {
    int i = blockIdx.x * blockDim.x + threadIdx.x;
    if (i < NGRAPH * DIM) { g_hs[i] = 0.0f; g_cs[i] = 0.0f; }
    if (i < NGRAPH * 2 * DIM) g_qstar[i] = 0.0f;   // full 131072 elements
    if (i <= N) g_counts[i] = 0;
}

// ---------------- per-graph node ranges from sorted batch --------------------
__global__ void offsets_kernel(const void* batch, int N) {
    int n = blockIdx.x * blockDim.x + threadIdx.x;
    if (n >= N) return;
    int is64 = g_is64;
    int b = (int)ld_idx(batch, n, is64);
    if (n == 0) {
        for (int g = 0; g <= b; g++) g_start[g] = 0;
    } else {
        int prev = (int)ld_idx(batch, n - 1, is64);
        if (prev != b)
            for (int g = prev + 1; g <= b; g++) g_start[g] = n;
    }
    if (n == N - 1)
        for (int g = b + 1; g <= NGRAPH; g++) g_start[g] = N;
}

// ---------------- CSR build: histogram of dst --------------------------------
__global__ void hist_kernel(const void* __restrict__ edge, long long E) {
    long long e = (long long)blockIdx.x * blockDim.x + threadIdx.x;
    if (e >= E) return;
    int d = (int)ld_idx(edge, E + e, g_is64);
    atomicAdd(&g_counts[d], 1);
}

// ---------------- CSR build: single-block exclusive scan ---------------------
__global__ void scan_kernel(int N) {
    __shared__ int ssum[1024];
    int t = threadIdx.x;
    int chunk = (N + 1023) / 1024;
    int lo = t * chunk;
    int hi = lo + chunk; if (hi > N) hi = N;
    int s = 0;
    for (int i = lo; i < hi; i++) s += g_counts[i];
    ssum[t] = s;
    __syncthreads();
    for (int off = 1; off < 1024; off <<= 1) {
        int v = (t >= off) ? ssum[t - off] : 0;
        __syncthreads();
        ssum[t] += v;
        __syncthreads();
    }
    int run = (t == 0) ? 0 : ssum[t - 1];   // exclusive base
    for (int i = lo; i < hi; i++) {
        g_rowptr[i] = run;
        g_cursor[i] = run;
        run += g_counts[i];
    }
    if (t == 1023) g_rowptr[N] = ssum[1023];
}

// ---------------- CSR build: fill src lists ----------------------------------
__global__ void fill_kernel(const void* __restrict__ edge, long long E) {
    long long e = (long long)blockIdx.x * blockDim.x + threadIdx.x;
    if (e >= E) return;
    int is64 = g_is64;
    int s = (int)ld_idx(edge, e, is64);
    int d = (int)ld_idx(edge, E + e, is64);
    int slot = atomicAdd(&g_cursor[d], 1);
    g_csr_src[slot] = s;
}

// ---------------- h0 = relu(x @ lin0_W + b); 32 nodes per block -------------
__global__ void lin0_kernel(const float* __restrict__ x,
                            const float* __restrict__ W,
                            const float* __restrict__ b, int N) {
    __shared__ float sW[INDIM * DIM];      // 6.4 KB
    __shared__ float sx[32][INDIM];        // 3.2 KB
    int tid = threadIdx.x;
    for (int i = tid; i < INDIM * DIM; i += 256) sW[i] = W[i];
    int node0 = blockIdx.x * 32;
    long long xbase = (long long)node0 * INDIM;
    int navail = N - node0; if (navail > 32) navail = 32;
    int tot = navail * INDIM;
    for (int i = tid; i < tot; i += 256)
        sx[i / INDIM][i % INDIM] = x[xbase + i];
    __syncthreads();
    int c = tid & 63;
    int ng = tid >> 6;                      // node group 0..3 (8 nodes each)
    float bc = b[c];
    float acc[8];
#pragma unroll
    for (int j = 0; j < 8; j++) acc[j] = bc;
#pragma unroll
    for (int k = 0; k < INDIM; k++) {
        float w = sW[k * DIM + c];
#pragma unroll
        for (int j = 0; j < 8; j++) acc[j] += sx[ng * 8 + j][k] * w;
    }
#pragma unroll
    for (int j = 0; j < 8; j++) {
        int n = node0 + ng * 8 + j;
        if (n < N) g_h0[(long long)n * DIM + c] = fmaxf(acc[j], 0.0f);
    }
}

// ------- fused: aggr = h0 + CSR-gather(h0);  h1 = relu(aggr @ gin_W + b) -----
__global__ __launch_bounds__(1024) void gather_gin_kernel(
        const float* __restrict__ W, const float* __restrict__ b, int N) {
    __shared__ float sW[DIM * DIM];        // 16 KB
    __shared__ float srow[32][DIM];        // 8 KB
    int tid = threadIdx.x;
    for (int i = tid; i < DIM * DIM; i += 1024) sW[i] = W[i];
    int w = tid >> 5, lane = tid & 31;
    int node = blockIdx.x * 32 + w;
    float2 acc = make_float2(0.0f, 0.0f);
    if (node < N) {
        acc = *(const float2*)&g_h0[(long long)node * DIM + 2 * lane];
        int r0 = g_rowptr[node], r1 = g_rowptr[node + 1];
        for (int j = r0; j < r1; j++) {
            int s = g_csr_src[j];          // broadcast across warp
            float2 v = *(const float2*)&g_h0[(long long)s * DIM + 2 * lane];
            acc.x += v.x; acc.y += v.y;
        }
    }
    *(float2*)&srow[w][2 * lane] = acc;
    __syncthreads();
    int n2 = tid >> 5;
    int c = tid & 31;
    int node2 = blockIdx.x * 32 + n2;
    if (node2 >= N) return;
    float a0 = b[c], a1 = b[c + 32];
#pragma unroll
    for (int k = 0; k < DIM; k++) {
        float r = srow[n2][k];             // warp broadcast
        a0 += r * sW[k * DIM + c];
        a1 += r * sW[k * DIM + c + 32];
    }
    long long o = (long long)node2 * DIM;
    g_h1[o + c]      = fmaxf(a0, 0.0f);
    g_h1[o + c + 32] = fmaxf(a1, 0.0f);
}

// ---------------- LSTM cell over 16 graphs per block -------------------------
__global__ void lstm_kernel(const float* __restrict__ W_ih,
                            const float* __restrict__ W_hh,
                            const float* __restrict__ b_ih,
                            const float* __restrict__ b_hh) {
    __shared__ float s[16 * 192];
    __shared__ float gates[16 * 256];
    int tid = threadIdx.x;
    int gb = blockIdx.x * 16;
    for (int i = tid; i < 16 * 192; i += blockDim.x) {
        int g = i / 192, k = i % 192;
        s[i] = (k < 128) ? g_qstar[(gb + g) * 128 + k]
                         : g_hs[(gb + g) * 64 + (k - 128)];
    }
    __syncthreads();
    int r = tid;
    float acc[16];
    float bsum = b_ih[r] + b_hh[r];
#pragma unroll
    for (int g = 0; g < 16; g++) acc[g] = bsum;
    const float* wi = &W_ih[r * 128];
    for (int k = 0; k < 128; k++) {
        float w = wi[k];
#pragma unroll
        for (int g = 0; g < 16; g++) acc[g] += w * s[g * 192 + k];
    }
    const float* wh = &W_hh[r * 64];
    for (int k = 0; k < 64; k++) {
        float w = wh[k];
#pragma unroll
        for (int g = 0; g < 16; g++) acc[g] += w * s[g * 192 + 128 + k];
    }
#pragma unroll
    for (int g = 0; g < 16; g++) gates[g * 256 + r] = acc[g];
    __syncthreads();
    for (int cell = tid; cell < 16 * 64; cell += blockDim.x) {
        int g = cell >> 6, u = cell & 63;
        int gg = gb + g;
        float iv = gates[g * 256 + u];
        float fv = gates[g * 256 + 64 + u];
        float gv = gates[g * 256 + 128 + u];
        float ov = gates[g * 256 + 192 + u];
        float c_old = g_cs[gg * 64 + u];
        float c_new = sigm(fv) * c_old + sigm(iv) * tanhf(gv);
        float h_new = sigm(ov) * tanhf(c_new);
        g_cs[gg * 64 + u] = c_new;
        g_hs[gg * 64 + u] = h_new;
        g_qstar[gg * 128 + u] = h_new;
    }
}

// -------- per-graph softmax attention, single pass (online softmax) ----------
__global__ void attn_kernel() {
    __shared__ float qsh[DIM];
    __shared__ float rsh[4][DIM];
    __shared__ float dsh[4];
    __shared__ float msh[4];
    int g = blockIdx.x;
    int tid = threadIdx.x;
    int warp = tid >> 5, lane = tid & 31;
    if (tid < DIM) qsh[tid] = g_hs[g * DIM + tid];
    __syncthreads();
    int s0 = g_start[g], s1 = g_start[g + 1];
    float qa = qsh[2 * lane], qb = qsh[2 * lane + 1];
    float m = -1e30f, d = 0.0f, rx = 0.0f, ry = 0.0f;
    for (int n = s0 + warp; n < s1; n += 4) {
        float2 hv = *(const float2*)&g_h1[(long long)n * DIM + 2 * lane];
        float p = hv.x * qa + hv.y * qb;
#pragma unroll
        for (int off = 16; off > 0; off >>= 1) p += __shfl_xor_sync(0xFFFFFFFF, p, off);
        float mn = fmaxf(m, p);
        float sc = __expf(m - mn);
        float w = __expf(p - mn);
        d  = d * sc + w;
        rx = rx * sc + w * hv.x;
        ry = ry * sc + w * hv.y;
        m = mn;
    }
    rsh[warp][2 * lane]     = rx;
    rsh[warp][2 * lane + 1] = ry;
    if (lane == 0) { dsh[warp] = d; msh[warp] = m; }
    __syncthreads();
    if (tid < DIM) {
        float gm = fmaxf(fmaxf(msh[0], msh[1]), fmaxf(msh[2], msh[3]));
        float r = 0.0f, den = 0.0f;
#pragma unroll
        for (int w = 0; w < 4; w++) {
            float sc = (msh[w] > -1e29f) ? __expf(msh[w] - gm) : 0.0f;
            r   += rsh[w][tid] * sc;
            den += dsh[w] * sc;
        }
        if (den == 0.0f) den = 1.0f;
        g_qstar[g * 128 + DIM + tid] = r / den;
    }
}

// ---------------- head: out = relu(q_star@lin1+b1) @ lin2 + b2 --------------
__global__ void head_kernel(const float* __restrict__ lin1_W,
                            const float* __restrict__ lin1_b,
                            const float* __restrict__ lin2_W,
                            const float* __restrict__ lin2_b,
                            float* __restrict__ out) {
    __shared__ float qs[128];
    __shared__ float red[64];
    int g = blockIdx.x;
    int t = threadIdx.x;
    qs[t] = g_qstar[g * 128 + t];
    qs[t + 64] = g_qstar[g * 128 + t + 64];
    __syncthreads();
    float acc = lin1_b[t];
#pragma unroll 8
    for (int k = 0; k < 128; k++) acc += qs[k] * lin1_W[k * 64 + t];
    acc = fmaxf(acc, 0.0f);
    red[t] = acc * lin2_W[t];
    __syncthreads();
    if (t < 32) {
        float v = red[t] + red[t + 32];
#pragma unroll
        for (int off = 16; off > 0; off >>= 1) v += __shfl_xor_sync(0xFFFFFFFF, v, off);
        if (t == 0) out[g] = v + lin2_b[0];
    }
}

// ---------------- launch ------------------------------------------------------
extern "C" void kernel_launch(void* const* d_in, const int* in_sizes, int n_in,
                              void* d_out, int out_size) {
    const float* x      = (const float*)d_in[0];
    const void*  edge   = d_in[1];
    const void*  batch  = d_in[2];
    const float* lin0_W = (const float*)d_in[3];
    const float* lin0_b = (const float*)d_in[4];
    const float* gin_W  = (const float*)d_in[5];
    const float* gin_b  = (const float*)d_in[6];
    const float* W_ih   = (const float*)d_in[7];
    const float* W_hh   = (const float*)d_in[8];
    const float* b_ih   = (const float*)d_in[9];
    const float* b_hh   = (const float*)d_in[10];
    const float* lin1_W = (const float*)d_in[11];
    const float* lin1_b = (const float*)d_in[12];
    const float* lin2_W = (const float*)d_in[13];
    const float* lin2_b = (const float*)d_in[14];
    float* out = (float*)d_out;

    int N = in_sizes[0] / INDIM;
    long long E = (long long)in_sizes[1] / 2;

    // init must cover BOTH q_star (131072) and counts (N+1)
    int init_elems = NGRAPH * 2 * DIM;
    if (N + 1 > init_elems) init_elems = N + 1;

    detect_kernel<<<1, 256>>>(batch, N);
    init_kernel<<<(init_elems + 255) / 256, 256>>>(N);
    offsets_kernel<<<(N + 255) / 256, 256>>>(batch, N);
    hist_kernel<<<(unsigned)((E + 255) / 256), 256>>>(edge, E);
    scan_kernel<<<1, 1024>>>(N);
    fill_kernel<<<(unsigned)((E + 255) / 256), 256>>>(edge, E);
    lin0_kernel<<<(N + 31) / 32, 256>>>(x, lin0_W, lin0_b, N);
    gather_gin_kernel<<<(N + 31) / 32, 1024>>>(gin_W, gin_b, N);
    for (int step = 0; step < 3; step++) {
        lstm_kernel<<<NGRAPH / 16, 256>>>(W_ih, W_hh, b_ih, b_hh);
        attn_kernel<<<NGRAPH, 128>>>();
    }
    head_kernel<<<NGRAPH, 64>>>(lin1_W, lin1_b, lin2_W, lin2_b, out);
}

// round 6
// speedup vs baseline: 1.0454x; 1.0454x over previous
#include <cuda_runtime.h>
#include <math.h>

#define NGRAPH 1024
#define DIM 64
#define INDIM 25
#define MAXN 100000
#define MAXE 1600000

// ---------------- scratch (device globals; no allocation allowed) ----------
__device__ __align__(16) float g_h0[MAXN * DIM];
__device__ __align__(16) float g_h1[MAXN * DIM];
__device__ int   g_counts[MAXN + 1];
__device__ int   g_rowptr[MAXN + 1];
__device__ int   g_cursor[MAXN + 1];
__device__ int   g_csr_src[MAXE];
__device__ int   g_start[NGRAPH + 1];
__device__ float g_hs[NGRAPH * DIM];
__device__ float g_cs[NGRAPH * DIM];
__device__ float g_qstar[NGRAPH * 2 * DIM];
__device__ float g_Wt[192 * 256];      // transposed LSTM weights [k][r]
__device__ float g_bias[256];          // b_ih + b_hh
__device__ int   g_is64;

// ---------------- helpers ---------------------------------------------------
__device__ __forceinline__ long long ld_idx(const void* p, long long i, int is64) {
    return is64 ? ((const long long*)p)[i] : (long long)((const int*)p)[i];
}
__device__ __forceinline__ float sigm(float x) { return 1.0f / (1.0f + __expf(-x)); }

// ---------------- dtype detection (int32 vs int64 indices) ------------------
__global__ void detect_kernel(const void* batch, int N) {
    __shared__ int nz;
    if (threadIdx.x == 0) nz = 0;
    __syncthreads();
    int limit = N < 20000 ? N : 20000;
    int cnt = 0;
    for (int i = 1 + 2 * (int)threadIdx.x; i < limit; i += 2 * blockDim.x)
        if (((const int*)batch)[i] != 0) cnt++;
    if (cnt) atomicAdd(&nz, cnt);
    __syncthreads();
    if (threadIdx.x == 0) g_is64 = (nz == 0) ? 1 : 0;
}

// ----- zero LSTM state, q_star, degree counts (covers every replay) ---------
__global__ void init_kernel(int N) {
    int i = blockIdx.x * blockDim.x + threadIdx.x;
    if (i < NGRAPH * DIM) { g_hs[i] = 0.0f; g_cs[i] = 0.0f; }
    if (i < NGRAPH * 2 * DIM) g_qstar[i] = 0.0f;
    if (i <= N) g_counts[i] = 0;
}

// ---------------- per-graph node ranges from sorted batch --------------------
__global__ void offsets_kernel(const void* batch, int N) {
    int n = blockIdx.x * blockDim.x + threadIdx.x;
    if (n >= N) return;
    int is64 = g_is64;
    int b = (int)ld_idx(batch, n, is64);
    if (n == 0) {
        for (int g = 0; g <= b; g++) g_start[g] = 0;
    } else {
        int prev = (int)ld_idx(batch, n - 1, is64);
        if (prev != b)
            for (int g = prev + 1; g <= b; g++) g_start[g] = n;
    }
    if (n == N - 1)
        for (int g = b + 1; g <= NGRAPH; g++) g_start[g] = N;
}

// ---------------- CSR build: histogram of dst --------------------------------
__global__ void hist_kernel(const void* __restrict__ edge, long long E) {
    long long e = (long long)blockIdx.x * blockDim.x + threadIdx.x;
    if (e >= E) return;
    int d = (int)ld_idx(edge, E + e, g_is64);
    atomicAdd(&g_counts[d], 1);
}

// ---------------- CSR build: single-block exclusive scan ---------------------
__global__ void scan_kernel(int N) {
    __shared__ int ssum[1024];
    int t = threadIdx.x;
    int chunk = (N + 1023) / 1024;
    int lo = t * chunk;
    int hi = lo + chunk; if (hi > N) hi = N;
    int s = 0;
    for (int i = lo; i < hi; i++) s += g_counts[i];
    ssum[t] = s;
    __syncthreads();
    for (int off = 1; off < 1024; off <<= 1) {
        int v = (t >= off) ? ssum[t - off] : 0;
        __syncthreads();
        ssum[t] += v;
        __syncthreads();
    }
    int run = (t == 0) ? 0 : ssum[t - 1];
    for (int i = lo; i < hi; i++) {
        g_rowptr[i] = run;
        g_cursor[i] = run;
        run += g_counts[i];
    }
    if (t == 1023) g_rowptr[N] = ssum[1023];
}

// ---------------- CSR build: fill src lists ----------------------------------
__global__ void fill_kernel(const void* __restrict__ edge, long long E) {
    long long e = (long long)blockIdx.x * blockDim.x + threadIdx.x;
    if (e >= E) return;
    int is64 = g_is64;
    int s = (int)ld_idx(edge, e, is64);
    int d = (int)ld_idx(edge, E + e, is64);
    int slot = atomicAdd(&g_cursor[d], 1);
    g_csr_src[slot] = s;
}

// ---------------- LSTM weight transpose (once per call) ----------------------
__global__ void transpose_kernel(const float* __restrict__ W_ih,
                                 const float* __restrict__ W_hh,
                                 const float* __restrict__ b_ih,
                                 const float* __restrict__ b_hh) {
    int idx = blockIdx.x * blockDim.x + threadIdx.x;
    if (idx < 256 * 128) {                      // W_ih: [256][128]
        int r = idx >> 7, k = idx & 127;
        g_Wt[k * 256 + r] = W_ih[idx];
    } else if (idx < 256 * 128 + 256 * 64) {    // W_hh: [256][64]
        int j = idx - 256 * 128;
        int r = j >> 6, k = j & 63;
        g_Wt[(128 + k) * 256 + r] = W_hh[j];
    }
    if (idx < 256) g_bias[idx] = b_ih[idx] + b_hh[idx];
}

// ---------------- h0 = relu(x @ lin0_W + b); 32 nodes per block -------------
__global__ void lin0_kernel(const float* __restrict__ x,
                            const float* __restrict__ W,
                            const float* __restrict__ b, int N) {
    __shared__ float sW[INDIM * DIM];
    __shared__ float sx[32][INDIM];
    int tid = threadIdx.x;
    for (int i = tid; i < INDIM * DIM; i += 256) sW[i] = W[i];
    int node0 = blockIdx.x * 32;
    long long xbase = (long long)node0 * INDIM;
    int navail = N - node0; if (navail > 32) navail = 32;
    int tot = navail * INDIM;
    for (int i = tid; i < tot; i += 256)
        sx[i / INDIM][i % INDIM] = x[xbase + i];
    __syncthreads();
    int c = tid & 63;
    int ng = tid >> 6;
    float bc = b[c];
    float acc[8];
#pragma unroll
    for (int j = 0; j < 8; j++) acc[j] = bc;
#pragma unroll
    for (int k = 0; k < INDIM; k++) {
        float w = sW[k * DIM + c];
#pragma unroll
        for (int j = 0; j < 8; j++) acc[j] += sx[ng * 8 + j][k] * w;
    }
#pragma unroll
    for (int j = 0; j < 8; j++) {
        int n = node0 + ng * 8 + j;
        if (n < N) g_h0[(long long)n * DIM + c] = fmaxf(acc[j], 0.0f);
    }
}

// ------- fused: aggr = h0 + CSR-gather(h0);  h1 = relu(aggr @ gin_W + b) -----
// Phase 1: warp gathers 4 nodes, pipelined (shuffle-batched indices, MLP>=4).
// Phase 2: register-blocked matmul, thread = 2 nodes x 4 cols, float4 LDS.
__global__ __launch_bounds__(256) void gather_gin_kernel(
        const float* __restrict__ W, const float* __restrict__ b, int N) {
    __shared__ float sW[DIM * DIM];        // 16 KB, W[k][c]
    __shared__ float srow[32][DIM];        // 8 KB
    int tid = threadIdx.x;
    for (int i = tid; i < DIM * DIM; i += 256) sW[i] = W[i];
    int w = tid >> 5, lane = tid & 31;
    int node0 = blockIdx.x * 32;
    // ---- phase 1: gather (warp w handles local nodes w*4 .. w*4+3)
#pragma unroll
    for (int i = 0; i < 4; i++) {
        int nl = w * 4 + i;
        int node = node0 + nl;
        float ax = 0.0f, ay = 0.0f;
        if (node < N) {
            float2 self = *(const float2*)&g_h0[(long long)node * DIM + 2 * lane];
            ax = self.x; ay = self.y;
            int r0 = g_rowptr[node], r1 = g_rowptr[node + 1];
            int j = r0;
            while (j < r1) {
                int cnt = r1 - j; if (cnt > 32) cnt = 32;
                int my = 0;
                if (lane < cnt) my = g_csr_src[j + lane];   // coalesced batch
                int t = 0;
                for (; t + 4 <= cnt; t += 4) {
                    int s0 = __shfl_sync(0xFFFFFFFF, my, t);
                    int s1 = __shfl_sync(0xFFFFFFFF, my, t + 1);
                    int s2 = __shfl_sync(0xFFFFFFFF, my, t + 2);
                    int s3 = __shfl_sync(0xFFFFFFFF, my, t + 3);
                    float2 v0 = *(const float2*)&g_h0[(long long)s0 * DIM + 2 * lane];
                    float2 v1 = *(const float2*)&g_h0[(long long)s1 * DIM + 2 * lane];
                    float2 v2 = *(const float2*)&g_h0[(long long)s2 * DIM + 2 * lane];
                    float2 v3 = *(const float2*)&g_h0[(long long)s3 * DIM + 2 * lane];
                    ax += v0.x + v1.x + v2.x + v3.x;
                    ay += v0.y + v1.y + v2.y + v3.y;
                }
                for (; t < cnt; t++) {
                    int s = __shfl_sync(0xFFFFFFFF, my, t);
                    float2 v = *(const float2*)&g_h0[(long long)s * DIM + 2 * lane];
                    ax += v.x; ay += v.y;
                }
                j += cnt;
            }
        }
        srow[nl][2 * lane]     = ax;
        srow[nl][2 * lane + 1] = ay;
    }
    __syncthreads();
    // ---- phase 2: h1 = relu(srow @ W + b), thread = nodes {p, p+16} x 4 cols
    int p  = tid >> 4;               // 0..15
    int c4 = (tid & 15) * 4;         // 0,4,...,60
    float acc0[4], acc1[4];
#pragma unroll
    for (int j = 0; j < 4; j++) { acc0[j] = b[c4 + j]; acc1[j] = acc0[j]; }
#pragma unroll 4
    for (int k0 = 0; k0 < DIM; k0 += 4) {
        float4 ra = *(const float4*)&srow[p][k0];
        float4 rb = *(const float4*)&srow[p + 16][k0];
#pragma unroll
        for (int kk = 0; kk < 4; kk++) {
            float4 wv = *(const float4*)&sW[(k0 + kk) * DIM + c4];
            float rav = (kk == 0) ? ra.x : (kk == 1) ? ra.y : (kk == 2) ? ra.z : ra.w;
            float rbv = (kk == 0) ? rb.x : (kk == 1) ? rb.y : (kk == 2) ? rb.z : rb.w;
            acc0[0] += rav * wv.x; acc0[1] += rav * wv.y;
            acc0[2] += rav * wv.z; acc0[3] += rav * wv.w;
            acc1[0] += rbv * wv.x; acc1[1] += rbv * wv.y;
            acc1[2] += rbv * wv.z; acc1[3] += rbv * wv.w;
        }
    }
    int nodeA = node0 + p, nodeB = node0 + p + 16;
    if (nodeA < N) {
        float4 o = make_float4(fmaxf(acc0[0], 0.f), fmaxf(acc0[1], 0.f),
                               fmaxf(acc0[2], 0.f), fmaxf(acc0[3], 0.f));
        *(float4*)&g_h1[(long long)nodeA * DIM + c4] = o;
    }
    if (nodeB < N) {
        float4 o = make_float4(fmaxf(acc1[0], 0.f), fmaxf(acc1[1], 0.f),
                               fmaxf(acc1[2], 0.f), fmaxf(acc1[3], 0.f));
        *(float4*)&g_h1[(long long)nodeB * DIM + c4] = o;
    }
}

// ---------------- LSTM cell, 16 graphs/block, coalesced transposed weights ---
__global__ void lstm_kernel() {
    __shared__ float s[16 * 192];
    __shared__ float gates[16 * 256];
    int tid = threadIdx.x;
    int gb = blockIdx.x * 16;
    for (int i = tid; i < 16 * 192; i += 256) {
        int g = i / 192, k = i % 192;
        s[i] = (k < 128) ? g_qstar[(gb + g) * 128 + k]
                         : g_hs[(gb + g) * 64 + (k - 128)];
    }
    __syncthreads();
    int r = tid;
    float acc[16];
    float bsum = g_bias[r];
#pragma unroll
    for (int g = 0; g < 16; g++) acc[g] = bsum;
    for (int k = 0; k < 192; k++) {
        float wv = g_Wt[k * 256 + r];          // coalesced
#pragma unroll
        for (int g = 0; g < 16; g++) acc[g] += wv * s[g * 192 + k];
    }
#pragma unroll
    for (int g = 0; g < 16; g++) gates[g * 256 + r] = acc[g];
    __syncthreads();
    for (int cell = tid; cell < 16 * 64; cell += 256) {
        int g = cell >> 6, u = cell & 63;
        int gg = gb + g;
        float iv = gates[g * 256 + u];
        float fv = gates[g * 256 + 64 + u];
        float gv = gates[g * 256 + 128 + u];
        float ov = gates[g * 256 + 192 + u];
        float c_old = g_cs[gg * 64 + u];
        float c_new = sigm(fv) * c_old + sigm(iv) * tanhf(gv);
        float h_new = sigm(ov) * tanhf(c_new);
        g_cs[gg * 64 + u] = c_new;
        g_hs[gg * 64 + u] = h_new;
        g_qstar[gg * 128 + u] = h_new;
    }
}

// -------- per-graph softmax attention, single pass (online softmax) ----------
__global__ void attn_kernel() {
    __shared__ float qsh[DIM];
    __shared__ float rsh[4][DIM];
    __shared__ float dsh[4];
    __shared__ float msh[4];
    int g = blockIdx.x;
    int tid = threadIdx.x;
    int warp = tid >> 5, lane = tid & 31;
    if (tid < DIM) qsh[tid] = g_hs[g * DIM + tid];
    __syncthreads();
    int s0 = g_start[g], s1 = g_start[g + 1];
    float qa = qsh[2 * lane], qb = qsh[2 * lane + 1];
    float m = -1e30f, d = 0.0f, rx = 0.0f, ry = 0.0f;
    for (int n = s0 + warp; n < s1; n += 4) {
        float2 hv = *(const float2*)&g_h1[(long long)n * DIM + 2 * lane];
        float p = hv.x * qa + hv.y * qb;
#pragma unroll
        for (int off = 16; off > 0; off >>= 1) p += __shfl_xor_sync(0xFFFFFFFF, p, off);
        float mn = fmaxf(m, p);
        float sc = __expf(m - mn);
        float wt = __expf(p - mn);
        d  = d * sc + wt;
        rx = rx * sc + wt * hv.x;
        ry = ry * sc + wt * hv.y;
        m = mn;
    }
    rsh[warp][2 * lane]     = rx;
    rsh[warp][2 * lane + 1] = ry;
    if (lane == 0) { dsh[warp] = d; msh[warp] = m; }
    __syncthreads();
    if (tid < DIM) {
        float gm = fmaxf(fmaxf(msh[0], msh[1]), fmaxf(msh[2], msh[3]));
        float r = 0.0f, den = 0.0f;
#pragma unroll
        for (int w = 0; w < 4; w++) {
            float sc = (msh[w] > -1e29f) ? __expf(msh[w] - gm) : 0.0f;
            r   += rsh[w][tid] * sc;
            den += dsh[w] * sc;
        }
        if (den == 0.0f) den = 1.0f;
        g_qstar[g * 128 + DIM + tid] = r / den;
    }
}

// ---------------- head: out = relu(q_star@lin1+b1) @ lin2 + b2 --------------
__global__ void head_kernel(const float* __restrict__ lin1_W,
                            const float* __restrict__ lin1_b,
                            const float* __restrict__ lin2_W,
                            const float* __restrict__ lin2_b,
                            float* __restrict__ out) {
    __shared__ float qs[128];
    __shared__ float red[64];
    int g = blockIdx.x;
    int t = threadIdx.x;
    qs[t] = g_qstar[g * 128 + t];
    qs[t + 64] = g_qstar[g * 128 + t + 64];
    __syncthreads();
    float acc = lin1_b[t];
#pragma unroll 8
    for (int k = 0; k < 128; k++) acc += qs[k] * lin1_W[k * 64 + t];
    acc = fmaxf(acc, 0.0f);
    red[t] = acc * lin2_W[t];
    __syncthreads();
    if (t < 32) {
        float v = red[t] + red[t + 32];
#pragma unroll
        for (int off = 16; off > 0; off >>= 1) v += __shfl_xor_sync(0xFFFFFFFF, v, off);
        if (t == 0) out[g] = v + lin2_b[0];
    }
}

// ---------------- launch ------------------------------------------------------
extern "C" void kernel_launch(void* const* d_in, const int* in_sizes, int n_in,
                              void* d_out, int out_size) {
    const float* x      = (const float*)d_in[0];
    const void*  edge   = d_in[1];
    const void*  batch  = d_in[2];
    const float* lin0_W = (const float*)d_in[3];
    const float* lin0_b = (const float*)d_in[4];
    const float* gin_W  = (const float*)d_in[5];
    const float* gin_b  = (const float*)d_in[6];
    const float* W_ih   = (const float*)d_in[7];
    const float* W_hh   = (const float*)d_in[8];
    const float* b_ih   = (const float*)d_in[9];
    const float* b_hh   = (const float*)d_in[10];
    const float* lin1_W = (const float*)d_in[11];
    const float* lin1_b = (const float*)d_in[12];
    const float* lin2_W = (const float*)d_in[13];
    const float* lin2_b = (const float*)d_in[14];
    float* out = (float*)d_out;

    int N = in_sizes[0] / INDIM;
    long long E = (long long)in_sizes[1] / 2;

    int init_elems = NGRAPH * 2 * DIM;
    if (N + 1 > init_elems) init_elems = N + 1;

    detect_kernel<<<1, 256>>>(batch, N);
    init_kernel<<<(init_elems + 255) / 256, 256>>>(N);
    offsets_kernel<<<(N + 255) / 256, 256>>>(batch, N);
    hist_kernel<<<(unsigned)((E + 255) / 256), 256>>>(edge, E);
    transpose_kernel<<<(256 * 192 + 255) / 256, 256>>>(W_ih, W_hh, b_ih, b_hh);
    scan_kernel<<<1, 1024>>>(N);
    fill_kernel<<<(unsigned)((E + 255) / 256), 256>>>(edge, E);
    lin0_kernel<<<(N + 31) / 32, 256>>>(x, lin0_W, lin0_b, N);
    gather_gin_kernel<<<(N + 31) / 32, 256>>>(gin_W, gin_b, N);
    for (int step = 0; step < 3; step++) {
        lstm_kernel<<<NGRAPH / 16, 256>>>();
        attn_kernel<<<NGRAPH, 128>>>();
    }
    head_kernel<<<NGRAPH, 64>>>(lin1_W, lin1_b, lin2_W, lin2_b, out);
}

// round 9
// speedup vs baseline: 1.3971x; 1.3365x over previous
#include <cuda_runtime.h>
#include <math.h>

#define NGRAPH 1024
#define DIM 64
#define INDIM 25
#define MAXN 100000

// ---------------- scratch (device globals; no allocation allowed) ----------
__device__ __align__(16) float g_h0[MAXN * DIM];
__device__ __align__(16) float g_aggr[MAXN * DIM];
__device__ __align__(16) float g_h1[MAXN * DIM];
__device__ int   g_start[NGRAPH + 1];
__device__ float g_hs[NGRAPH * DIM];
__device__ float g_cs[NGRAPH * DIM];
__device__ float g_qstar[NGRAPH * 2 * DIM];
__device__ float g_Wt[192 * 256];      // transposed LSTM weights [k][r]
__device__ float g_bias[256];          // b_ih + b_hh
__device__ int   g_is64;

// ---------------- helpers ---------------------------------------------------
__device__ __forceinline__ long long ld_idx(const void* p, long long i, int is64) {
    return is64 ? ((const long long*)p)[i] : (long long)((const int*)p)[i];
}
__device__ __forceinline__ float sigm(float x) { return 1.0f / (1.0f + __expf(-x)); }

// ---------------- dtype detection (int32 vs int64 indices) ------------------
__global__ void detect_kernel(const void* batch, int N) {
    __shared__ int nz;
    if (threadIdx.x == 0) nz = 0;
    __syncthreads();
    int limit = N < 20000 ? N : 20000;
    int cnt = 0;
    for (int i = 1 + 2 * (int)threadIdx.x; i < limit; i += 2 * blockDim.x)
        if (((const int*)batch)[i] != 0) cnt++;
    if (cnt) atomicAdd(&nz, cnt);
    __syncthreads();
    if (threadIdx.x == 0) g_is64 = (nz == 0) ? 1 : 0;
}

// ----- zero LSTM state + q_star (covers every replay) -----------------------
__global__ void init_kernel() {
    int i = blockIdx.x * blockDim.x + threadIdx.x;
    if (i < NGRAPH * DIM) { g_hs[i] = 0.0f; g_cs[i] = 0.0f; }
    if (i < NGRAPH * 2 * DIM) g_qstar[i] = 0.0f;
}

// ---------------- per-graph node ranges from sorted batch --------------------
__global__ void offsets_kernel(const void* batch, int N) {
    int n = blockIdx.x * blockDim.x + threadIdx.x;
    if (n >= N) return;
    int is64 = g_is64;
    int b = (int)ld_idx(batch, n, is64);
    if (n == 0) {
        for (int g = 0; g <= b; g++) g_start[g] = 0;
    } else {
        int prev = (int)ld_idx(batch, n - 1, is64);
        if (prev != b)
            for (int g = prev + 1; g <= b; g++) g_start[g] = n;
    }
    if (n == N - 1)
        for (int g = b + 1; g <= NGRAPH; g++) g_start[g] = N;
}

// ---------------- LSTM weight transpose (once per call) ----------------------
__global__ void transpose_kernel(const float* __restrict__ W_ih,
                                 const float* __restrict__ W_hh,
                                 const float* __restrict__ b_ih,
                                 const float* __restrict__ b_hh) {
    int idx = blockIdx.x * blockDim.x + threadIdx.x;
    if (idx < 256 * 128) {                      // W_ih: [256][128]
        int r = idx >> 7, k = idx & 127;
        g_Wt[k * 256 + r] = W_ih[idx];
    } else if (idx < 256 * 128 + 256 * 64) {    // W_hh: [256][64]
        int j = idx - 256 * 128;
        int r = j >> 6, k = j & 63;
        g_Wt[(128 + k) * 256 + r] = W_hh[j];
    }
    if (idx < 256) g_bias[idx] = b_ih[idx] + b_hh[idx];
}

// ------ h0 = relu(x @ lin0_W + b); aggr initialized to h0; 32 nodes/block ---
__global__ void lin0_kernel(const float* __restrict__ x,
                            const float* __restrict__ W,
                            const float* __restrict__ b, int N) {
    __shared__ float sW[INDIM * DIM];
    __shared__ float sx[32][INDIM];
    int tid = threadIdx.x;
    for (int i = tid; i < INDIM * DIM; i += 256) sW[i] = W[i];
    int node0 = blockIdx.x * 32;
    long long xbase = (long long)node0 * INDIM;
    int navail = N - node0; if (navail > 32) navail = 32;
    int tot = navail * INDIM;
    for (int i = tid; i < tot; i += 256)
        sx[i / INDIM][i % INDIM] = x[xbase + i];
    __syncthreads();
    int c = tid & 63;
    int ng = tid >> 6;                      // node group 0..3 (8 nodes each)
    float bc = b[c];
    float acc[8];
#pragma unroll
    for (int j = 0; j < 8; j++) acc[j] = bc;
#pragma unroll
    for (int k = 0; k < INDIM; k++) {
        float w = sW[k * DIM + c];
#pragma unroll
        for (int j = 0; j < 8; j++) acc[j] += sx[ng * 8 + j][k] * w;
    }
#pragma unroll
    for (int j = 0; j < 8; j++) {
        int n = node0 + ng * 8 + j;
        if (n < N) {
            float v = fmaxf(acc[j], 0.0f);
            long long o = (long long)n * DIM + c;
            g_h0[o] = v;
            g_aggr[o] = v;
        }
    }
}

// ---------------- edge scatter: aggr[dst] += h0[src] (vector RED) -----------
__global__ void scatter_kernel(const void* __restrict__ edge, long long E) {
    long long t = (long long)blockIdx.x * blockDim.x + threadIdx.x;
    long long total = E * 16;
    if (t >= total) return;
    int is64 = g_is64;
    long long e = t >> 4;
    int q = (int)(t & 15);
    long long s = ld_idx(edge, e, is64);
    long long d = ld_idx(edge, E + e, is64);
    float4 v = *(const float4*)&g_h0[s * DIM + q * 4];
    float* dst = &g_aggr[d * DIM + q * 4];
    unsigned long long gaddr = (unsigned long long)__cvta_generic_to_global(dst);
    asm volatile("red.global.add.v4.f32 [%0], {%1, %2, %3, %4};"
                 :: "l"(gaddr), "f"(v.x), "f"(v.y), "f"(v.z), "f"(v.w)
                 : "memory");
}

// ------- h1 = relu(aggr @ gin_W + b); 32 nodes/block, reg-blocked ------------
__global__ __launch_bounds__(256) void gin_kernel(
        const float* __restrict__ W, const float* __restrict__ b, int N) {
    __shared__ float sW[DIM * DIM];        // 16 KB
    __shared__ float srow[32][DIM];        // 8 KB
    int tid = threadIdx.x;
    for (int i = tid; i < DIM * DIM; i += 256) sW[i] = W[i];
    int node0 = blockIdx.x * 32;
    // coalesced float4 load of 32 rows of aggr
    int navail = N - node0; if (navail > 32) navail = 32;
    int tot4 = navail * (DIM / 4);          // float4 count
    long long abase = (long long)node0 * DIM;
    for (int i = tid; i < tot4; i += 256) {
        float4 v = *(const float4*)&g_aggr[abase + i * 4];
        *(float4*)&srow[i / 16][(i % 16) * 4] = v;
    }
    __syncthreads();
    // matmul: thread = nodes {p, p+16} x 4 cols
    int p  = tid >> 4;               // 0..15
    int c4 = (tid & 15) * 4;         // 0,4,...,60
    float acc0[4], acc1[4];
#pragma unroll
    for (int j = 0; j < 4; j++) { acc0[j] = b[c4 + j]; acc1[j] = acc0[j]; }
#pragma unroll 4
    for (int k0 = 0; k0 < DIM; k0 += 4) {
        float4 ra = *(const float4*)&srow[p][k0];
        float4 rb = *(const float4*)&srow[p + 16][k0];
#pragma unroll
        for (int kk = 0; kk < 4; kk++) {
            float4 wv = *(const float4*)&sW[(k0 + kk) * DIM + c4];
            float rav = (kk == 0) ? ra.x : (kk == 1) ? ra.y : (kk == 2) ? ra.z : ra.w;
            float rbv = (kk == 0) ? rb.x : (kk == 1) ? rb.y : (kk == 2) ? rb.z : rb.w;
            acc0[0] += rav * wv.x; acc0[1] += rav * wv.y;
            acc0[2] += rav * wv.z; acc0[3] += rav * wv.w;
            acc1[0] += rbv * wv.x; acc1[1] += rbv * wv.y;
            acc1[2] += rbv * wv.z; acc1[3] += rbv * wv.w;
        }
    }
    int nodeA = node0 + p, nodeB = node0 + p + 16;
    if (nodeA < N) {
        float4 o = make_float4(fmaxf(acc0[0], 0.f), fmaxf(acc0[1], 0.f),
                               fmaxf(acc0[2], 0.f), fmaxf(acc0[3], 0.f));
        *(float4*)&g_h1[(long long)nodeA * DIM + c4] = o;
    }
    if (nodeB < N) {
        float4 o = make_float4(fmaxf(acc1[0], 0.f), fmaxf(acc1[1], 0.f),
                               fmaxf(acc1[2], 0.f), fmaxf(acc1[3], 0.f));
        *(float4*)&g_h1[(long long)nodeB * DIM + c4] = o;
    }
}

// ---------------- LSTM cell, 16 graphs/block, coalesced transposed weights ---
__global__ void lstm_kernel() {
    __shared__ float s[16 * 192];
    __shared__ float gates[16 * 256];
    int tid = threadIdx.x;
    int gb = blockIdx.x * 16;
    for (int i = tid; i < 16 * 192; i += 256) {
        int g = i / 192, k = i % 192;
        s[i] = (k < 128) ? g_qstar[(gb + g) * 128 + k]
                         : g_hs[(gb + g) * 64 + (k - 128)];
    }
    __syncthreads();
    int r = tid;
    float acc[16];
    float bsum = g_bias[r];
#pragma unroll
    for (int g = 0; g < 16; g++) acc[g] = bsum;
    for (int k = 0; k < 192; k++) {
        float wv = g_Wt[k * 256 + r];          // coalesced
#pragma unroll
        for (int g = 0; g < 16; g++) acc[g] += wv * s[g * 192 + k];
    }
#pragma unroll
    for (int g = 0; g < 16; g++) gates[g * 256 + r] = acc[g];
    __syncthreads();
    for (int cell = tid; cell < 16 * 64; cell += 256) {
        int g = cell >> 6, u = cell & 63;
        int gg = gb + g;
        float iv = gates[g * 256 + u];
        float fv = gates[g * 256 + 64 + u];
        float gv = gates[g * 256 + 128 + u];
        float ov = gates[g * 256 + 192 + u];
        float c_old = g_cs[gg * 64 + u];
        float c_new = sigm(fv) * c_old + sigm(iv) * tanhf(gv);
        float h_new = sigm(ov) * tanhf(c_new);
        g_cs[gg * 64 + u] = c_new;
        g_hs[gg * 64 + u] = h_new;
        g_qstar[gg * 128 + u] = h_new;
    }
}

// -------- per-graph softmax attention, single pass (online softmax) ----------
__global__ void attn_kernel() {
    __shared__ float qsh[DIM];
    __shared__ float rsh[4][DIM];
    __shared__ float dsh[4];
    __shared__ float msh[4];
    int g = blockIdx.x;
    int tid = threadIdx.x;
    int warp = tid >> 5, lane = tid & 31;
    if (tid < DIM) qsh[tid] = g_hs[g * DIM + tid];
    __syncthreads();
    int s0 = g_start[g], s1 = g_start[g + 1];
    float qa = qsh[2 * lane], qb = qsh[2 * lane + 1];
    float m = -1e30f, d = 0.0f, rx = 0.0f, ry = 0.0f;
    for (int n = s0 + warp; n < s1; n += 4) {
        float2 hv = *(const float2*)&g_h1[(long long)n * DIM + 2 * lane];
        float p = hv.x * qa + hv.y * qb;
#pragma unroll
        for (int off = 16; off > 0; off >>= 1) p += __shfl_xor_sync(0xFFFFFFFF, p, off);
        float mn = fmaxf(m, p);
        float sc = __expf(m - mn);
        float wt = __expf(p - mn);
        d  = d * sc + wt;
        rx = rx * sc + wt * hv.x;
        ry = ry * sc + wt * hv.y;
        m = mn;
    }
    rsh[warp][2 * lane]     = rx;
    rsh[warp][2 * lane + 1] = ry;
    if (lane == 0) { dsh[warp] = d; msh[warp] = m; }
    __syncthreads();
    if (tid < DIM) {
        float gm = fmaxf(fmaxf(msh[0], msh[1]), fmaxf(msh[2], msh[3]));
        float r = 0.0f, den = 0.0f;
#pragma unroll
        for (int w = 0; w < 4; w++) {
            float sc = (msh[w] > -1e29f) ? __expf(msh[w] - gm) : 0.0f;
            r   += rsh[w][tid] * sc;
            den += dsh[w] * sc;
        }
        if (den == 0.0f) den = 1.0f;
        g_qstar[g * 128 + DIM + tid] = r / den;
    }
}

// ---------------- head: out = relu(q_star@lin1+b1) @ lin2 + b2 --------------
__global__ void head_kernel(const float* __restrict__ lin1_W,
                            const float* __restrict__ lin1_b,
                            const float* __restrict__ lin2_W,
                            const float* __restrict__ lin2_b,
                            float* __restrict__ out) {
    __shared__ float qs[128];
    __shared__ float red[64];
    int g = blockIdx.x;
    int t = threadIdx.x;
    qs[t] = g_qstar[g * 128 + t];
    qs[t + 64] = g_qstar[g * 128 + t + 64];
    __syncthreads();
    float acc = lin1_b[t];
#pragma unroll 8
    for (int k = 0; k < 128; k++) acc += qs[k] * lin1_W[k * 64 + t];
    acc = fmaxf(acc, 0.0f);
    red[t] = acc * lin2_W[t];
    __syncthreads();
    if (t < 32) {
        float v = red[t] + red[t + 32];
#pragma unroll
        for (int off = 16; off > 0; off >>= 1) v += __shfl_xor_sync(0xFFFFFFFF, v, off);
        if (t == 0) out[g] = v + lin2_b[0];
    }
}

// ---------------- launch ------------------------------------------------------
extern "C" void kernel_launch(void* const* d_in, const int* in_sizes, int n_in,
                              void* d_out, int out_size) {
    const float* x      = (const float*)d_in[0];
    const void*  edge   = d_in[1];
    const void*  batch  = d_in[2];
    const float* lin0_W = (const float*)d_in[3];
    const float* lin0_b = (const float*)d_in[4];
    const float* gin_W  = (const float*)d_in[5];
    const float* gin_b  = (const float*)d_in[6];
    const float* W_ih   = (const float*)d_in[7];
    const float* W_hh   = (const float*)d_in[8];
    const float* b_ih   = (const float*)d_in[9];
    const float* b_hh   = (const float*)d_in[10];
    const float* lin1_W = (const float*)d_in[11];
    const float* lin1_b = (const float*)d_in[12];
    const float* lin2_W = (const float*)d_in[13];
    const float* lin2_b = (const float*)d_in[14];
    float* out = (float*)d_out;

    int N = in_sizes[0] / INDIM;
    long long E = (long long)in_sizes[1] / 2;

    detect_kernel<<<1, 256>>>(batch, N);
    init_kernel<<<(NGRAPH * 2 * DIM + 255) / 256, 256>>>();
    offsets_kernel<<<(N + 255) / 256, 256>>>(batch, N);
    transpose_kernel<<<(256 * 192 + 255) / 256, 256>>>(W_ih, W_hh, b_ih, b_hh);
    lin0_kernel<<<(N + 31) / 32, 256>>>(x, lin0_W, lin0_b, N);
    long long sc_threads = E * 16;
    scatter_kernel<<<(unsigned)((sc_threads + 255) / 256), 256>>>(edge, E);
    gin_kernel<<<(N + 31) / 32, 256>>>(gin_W, gin_b, N);
    for (int step = 0; step < 3; step++) {
        lstm_kernel<<<NGRAPH / 16, 256>>>();
        attn_kernel<<<NGRAPH, 128>>>();
    }
    head_kernel<<<NGRAPH, 64>>>(lin1_W, lin1_b, lin2_W, lin2_b, out);
}